// round 16
// baseline (speedup 1.0000x reference)
#include <cuda_runtime.h>
#include <cstdint>

#define NB 16
#define NS 2048
#define NH 512
#define NW 4
#define NL 2
#define NSP (NS + 2*NW)   // 2056
#define LN_EPS 1e-5f

#define BM 128
#define BN 128
#define BK 32
#define GT 128             // GEMM threads: 4 warps, 2x2, warp tile 64x64
#define ASTR 36
#define BSTR 136
#define ASZW (BM*ASTR)     // 4608 words
#define BSZW (BK*BSTR)     // 4352 words
#define STAGEW (ASZW + BSZW)          // 8960 words = 35840 B
#define SMEM_BYTES (3*STAGEW*4)       // 3-stage: 107520 B

// Weight scratch offsets (tf32-rounded copies)
#define OFF_WL  0
#define OFF_WR  (2048*512)
#define OFF_LW1 (2*2048*512)
#define OFF_LW2 (OFF_LW1 + NL*512*512)
#define OFF_RW1 (OFF_LW2 + NL*512*512)
#define OFF_RW2 (OFF_RW1 + NL*512*512)
#define WTOT    (OFF_RW2 + NL*512*512)

// Device scratch (allocation-free contract)
__device__ float g_padded[NB*NSP*NH];
__device__ float g_lo  [NB*NS*NH];
__device__ float g_ro  [NB*NS*NH];
__device__ float g_tmp [NB*NS*NH];
__device__ float g_tmp2[NB*NS*NH];
__device__ float g_hid [NB*NS*NH];
__device__ float g_hid2[NB*NS*NH];
__device__ float g_w   [WTOT];

__device__ __forceinline__ uint32_t f2t(float x){
    uint32_t u; asm("cvt.rna.tf32.f32 %0, %1;" : "=r"(u) : "f"(x)); return u;
}
__device__ __forceinline__ float f2tf(float x){ return __uint_as_float(f2t(x)); }
__device__ __forceinline__ uint32_t smem_u32(const void* p){
    uint32_t a;
    asm("{ .reg .u64 t; cvta.to.shared.u64 t, %1; cvt.u32.u64 %0, t; }" : "=r"(a) : "l"(p));
    return a;
}
__device__ __forceinline__ void cpa16(uint32_t dst, const void* src){
    asm volatile("cp.async.cg.shared.global [%0], [%1], 16;" :: "r"(dst), "l"(src));
}
__device__ __forceinline__ void cpa_commit(){
    asm volatile("cp.async.commit_group;" ::: "memory");
}
__device__ __forceinline__ void cpa_wait1(){
    asm volatile("cp.async.wait_group 1;" ::: "memory");
}

// ---------- Pre-passes (producer-side tf32 rounding, unchanged from R15) ----------
__global__ void build_inputs_kernel(const float* __restrict__ inp){
    int idx = blockIdx.x*blockDim.x + threadIdx.x;
    const int H4 = NH/4;
    const int total = NB*NS*H4;
    if (idx >= total) return;
    int h4 = idx % H4;
    int r  = (idx / H4) % NS;
    int b  = idx / (H4*NS);
    float4 v = reinterpret_cast<const float4*>(inp)[((size_t)b*NS + r)*H4 + h4];
    v.x = f2tf(v.x); v.y = f2tf(v.y); v.z = f2tf(v.z); v.w = f2tf(v.w);
    reinterpret_cast<float4*>(g_padded)[((size_t)b*NSP + (r+NW))*H4 + h4] = v;
}
__global__ void build_pads_kernel(const float* __restrict__ lp,
                                  const float* __restrict__ rp){
    int idx = blockIdx.x*blockDim.x + threadIdx.x;
    const int H4 = NH/4;
    const int total = NB*(2*NW)*H4;
    if (idx >= total) return;
    int h4 = idx % H4;
    int r  = (idx / H4) % (2*NW);
    int b  = idx / (H4*(2*NW));
    float4 v; int dst;
    if (r < NW){ v = reinterpret_cast<const float4*>(lp)[r*H4 + h4];      dst = r; }
    else       { v = reinterpret_cast<const float4*>(rp)[(r-NW)*H4 + h4]; dst = NW + NS + (r-NW); }
    v.x = f2tf(v.x); v.y = f2tf(v.y); v.z = f2tf(v.z); v.w = f2tf(v.w);
    reinterpret_cast<float4*>(g_padded)[((size_t)b*NSP + dst)*H4 + h4] = v;
}
__global__ void round_weights_kernel(const float* __restrict__ Wl, const float* __restrict__ Wr,
                                     const float* __restrict__ lw1, const float* __restrict__ lw2,
                                     const float* __restrict__ rw1, const float* __restrict__ rw2){
    int idx = blockIdx.x*blockDim.x + threadIdx.x;
    const int T4 = WTOT/4;
    if (idx >= T4) return;
    int e = idx*4;
    const float* src; int off;
    if      (e < OFF_WR) { src = Wl;  off = e - OFF_WL;  }
    else if (e < OFF_LW1){ src = Wr;  off = e - OFF_WR;  }
    else if (e < OFF_LW2){ src = lw1; off = e - OFF_LW1; }
    else if (e < OFF_RW1){ src = lw2; off = e - OFF_LW2; }
    else if (e < OFF_RW2){ src = rw1; off = e - OFF_RW1; }
    else                 { src = rw2; off = e - OFF_RW2; }
    float4 v = *reinterpret_cast<const float4*>(src + off);
    v.x = f2tf(v.x); v.y = f2tf(v.y); v.z = f2tf(v.z); v.w = f2tf(v.w);
    reinterpret_cast<float4*>(g_w)[idx] = v;
}

// ---------- GEMM: z-fused left/right, 3-stage cp.async, 1 sync/tile ----------
// blockIdx.z selects the (A,B,bias,C,resid) tuple. pmode: 1 = projection
// (A = g_padded view, aoff = z*(NW+1)); 0 = dense A row-stride K.
// mode: 0 C=round(relu(acc+bias)); 2 C=relu(acc+bias) fp32;
//       1 r=resid+acc+bias; C=r; scatter out_all (+out_last), colOff=z*NH.
__global__ __launch_bounds__(GT) void gemm_tf32_kernel(
    const float* __restrict__ A0, const float* __restrict__ A1,
    const float* __restrict__ B0, const float* __restrict__ B1,
    const float* __restrict__ bias0, const float* __restrict__ bias1,
    float* __restrict__ C0, float* __restrict__ C1,
    const float* __restrict__ resid0, const float* __restrict__ resid1,
    float* __restrict__ out_all, float* __restrict__ out_last,
    int K, int pmode, int mode, int layer)
{
    extern __shared__ __align__(16) uint32_t sm[];
    const int tid   = threadIdx.x;
    const int lane  = tid & 31;
    const int warp  = tid >> 5;
    const int group = lane >> 2;
    const int tid4  = lane & 3;
    const int by = blockIdx.y, bx = blockIdx.x, z = blockIdx.z;
    const float* A    = z ? A1 : A0;
    const float* Bw   = z ? B1 : B0;
    const float* bias = z ? bias1 : bias0;
    float*       C    = z ? C1 : C0;
    const float* resid= z ? resid1 : resid0;
    const int colOff  = z ? NH : 0;
    const int aoff    = z ? (NW+1) : 0;
    const uint32_t sb = smem_u32(sm);

    auto issue = [&](int buf, int kt){
        const int kb = kt*BK;
        uint32_t abase = sb + (uint32_t)buf*(STAGEW*4);
        const int arow = tid >> 3, achk = tid & 7;
        #pragma unroll
        for (int i = 0; i < 8; i++){
            int row = arow + i*16;
            const float* src;
            if (pmode == 0) src = A + (size_t)(by*BM + row)*K + kb + achk*4;
            else {
                int mrow = by*BM + row;
                int b = mrow >> 11, t = mrow & 2047;
                src = A + ((size_t)b*NSP + t + aoff)*NH + kb + achk*4;
            }
            cpa16(abase + row*144 + achk*16, src);
        }
        uint32_t bbase = abase + ASZW*4;
        const int brow = tid >> 5, bchk = tid & 31;
        #pragma unroll
        for (int i = 0; i < 8; i++){
            int row = brow + i*4;
            const float* src = Bw + (size_t)(kb + row)*NH + bx*BN + bchk*4;
            cpa16(bbase + row*544 + bchk*16, src);
        }
    };

    float acc[4][8][4];
    #pragma unroll
    for (int i=0;i<4;i++)
      #pragma unroll
      for (int j=0;j<8;j++)
        #pragma unroll
        for (int q=0;q<4;q++) acc[i][j][q]=0.f;

    const int ntiles = K / BK;
    issue(0, 0); cpa_commit();
    issue(1, 1); cpa_commit();

    const int wmb = (warp>>1)*64;
    const int wnb = (warp&1)*64;

    for (int kt = 0; kt < ntiles; kt++){
        cpa_wait1();
        __syncthreads();   // all warps done with buffer (kt+2)%3's previous life
        const uint32_t* As = sm + (kt%3)*STAGEW;
        const uint32_t* Bs = As + ASZW;
        #pragma unroll
        for (int kk = 0; kk < BK; kk += 8){
            uint32_t af[4][4], bf[8][2];
            #pragma unroll
            for (int mi=0; mi<4; mi++){
                int mr = wmb + mi*16 + group;
                af[mi][0] = As[mr*ASTR     + kk + tid4];
                af[mi][1] = As[(mr+8)*ASTR + kk + tid4];
                af[mi][2] = As[mr*ASTR     + kk + tid4 + 4];
                af[mi][3] = As[(mr+8)*ASTR + kk + tid4 + 4];
            }
            #pragma unroll
            for (int ni=0; ni<8; ni++){
                int nc = wnb + ni*8 + group;
                bf[ni][0] = Bs[(kk + tid4)*BSTR     + nc];
                bf[ni][1] = Bs[(kk + tid4 + 4)*BSTR + nc];
            }
            #pragma unroll
            for (int mi=0; mi<4; mi++)
                #pragma unroll
                for (int ni=0; ni<8; ni++){
                    asm volatile(
                        "mma.sync.aligned.m16n8k8.row.col.f32.tf32.tf32.f32 "
                        "{%0,%1,%2,%3}, {%4,%5,%6,%7}, {%8,%9}, {%0,%1,%2,%3};"
                        : "+f"(acc[mi][ni][0]), "+f"(acc[mi][ni][1]),
                          "+f"(acc[mi][ni][2]), "+f"(acc[mi][ni][3])
                        : "r"(af[mi][0]), "r"(af[mi][1]), "r"(af[mi][2]), "r"(af[mi][3]),
                          "r"(bf[ni][0]), "r"(bf[ni][1]));
                }
        }
        if (kt + 2 < ntiles) issue((kt+2)%3, kt+2);
        cpa_commit();
    }

    // Epilogue: warp tile 64x64
    const int m0 = by*BM + wmb;
    const int n0 = bx*BN + wnb;
    #pragma unroll
    for (int mi=0; mi<4; mi++){
        #pragma unroll
        for (int ni=0; ni<8; ni++){
            int rr = m0 + mi*16 + group;
            int cc = n0 + ni*8 + tid4*2;
            #pragma unroll
            for (int q=0;q<4;q++){
                int m = rr + ((q>=2) ? 8 : 0);
                int c = cc + (q&1);
                float v = acc[mi][ni][q] + __ldg(&bias[c]);
                size_t ci = (size_t)m*NH + c;
                if (mode == 0){
                    C[ci] = f2tf(fmaxf(v, 0.f));
                } else if (mode == 2){
                    C[ci] = fmaxf(v, 0.f);
                } else {
                    float res = resid[ci] + v;
                    C[ci] = res;
                    int b = m >> 11, s = m & 2047;
                    out_all[(((size_t)layer*NS + s)*NB + b)*(2*NH) + colOff + c] = res;
                    if (out_last) out_last[((size_t)m)*(2*NH) + colOff + c] = res;
                }
            }
        }
    }
}

// LayerNorm, z-fused: rows [0,32768) = left (x0,g0,b0 -> y0), [32768,65536) = right.
__global__ void ln_kernel(const float* __restrict__ x0, const float* __restrict__ x1,
                          const float* __restrict__ g0, const float* __restrict__ g1,
                          const float* __restrict__ be0, const float* __restrict__ be1,
                          float* __restrict__ y0, float* __restrict__ y1){
    int grow = blockIdx.x*8 + (threadIdx.x >> 5);
    int side = grow >> 15;
    int row  = grow & 32767;
    const float* x  = side ? x1 : x0;
    const float* g  = side ? g1 : g0;
    const float* be = side ? be1 : be0;
    float*       y  = side ? y1 : y0;
    int lane = threadIdx.x & 31;
    const float4* xr = reinterpret_cast<const float4*>(x + (size_t)row*NH);
    float4 v[4];
    float s = 0.f, ss = 0.f;
    #pragma unroll
    for (int i=0;i<4;i++){
        v[i] = xr[lane + i*32];
        s  += v[i].x + v[i].y + v[i].z + v[i].w;
        ss += v[i].x*v[i].x + v[i].y*v[i].y + v[i].z*v[i].z + v[i].w*v[i].w;
    }
    #pragma unroll
    for (int o=16;o>0;o>>=1){
        s  += __shfl_xor_sync(0xffffffff, s,  o);
        ss += __shfl_xor_sync(0xffffffff, ss, o);
    }
    float mean = s  * (1.f/NH);
    float var  = ss * (1.f/NH) - mean*mean;
    float rstd = rsqrtf(var + LN_EPS);
    float4* yr = reinterpret_cast<float4*>(y + (size_t)row*NH);
    #pragma unroll
    for (int i=0;i<4;i++){
        int c = (lane + i*32)*4;
        float4 o;
        o.x = f2tf(g[c+0]*((v[i].x-mean)*rstd) + be[c+0]);
        o.y = f2tf(g[c+1]*((v[i].y-mean)*rstd) + be[c+1]);
        o.z = f2tf(g[c+2]*((v[i].z-mean)*rstd) + be[c+2]);
        o.w = f2tf(g[c+3]*((v[i].w-mean)*rstd) + be[c+3]);
        yr[lane + i*32] = o;
    }
}

extern "C" void kernel_launch(void* const* d_in, const int* in_sizes, int n_in,
                              void* d_out, int out_size){
    const float* inputs = (const float*)d_in[0];
    const float* lp  = (const float*)d_in[1];
    const float* rp  = (const float*)d_in[2];
    const float* Wl  = (const float*)d_in[3];
    const float* bl  = (const float*)d_in[4];
    const float* Wr  = (const float*)d_in[5];
    const float* br_ = (const float*)d_in[6];
    const float* lw1 = (const float*)d_in[7];
    const float* lb1 = (const float*)d_in[8];
    const float* lw2 = (const float*)d_in[9];
    const float* lb2 = (const float*)d_in[10];
    const float* lg  = (const float*)d_in[11];
    const float* lbe = (const float*)d_in[12];
    const float* rw1 = (const float*)d_in[13];
    const float* rb1 = (const float*)d_in[14];
    const float* rw2 = (const float*)d_in[15];
    const float* rb2 = (const float*)d_in[16];
    const float* rg  = (const float*)d_in[17];
    const float* rbe = (const float*)d_in[18];

    float* out_all  = (float*)d_out;
    float* out_last = out_all + (size_t)NL*NS*NB*2*NH;

    float *p_pad, *p_lo, *p_ro, *p_tmp, *p_tmp2, *p_hid, *p_hid2, *p_w;
    cudaGetSymbolAddress((void**)&p_pad,  g_padded);
    cudaGetSymbolAddress((void**)&p_lo,   g_lo);
    cudaGetSymbolAddress((void**)&p_ro,   g_ro);
    cudaGetSymbolAddress((void**)&p_tmp,  g_tmp);
    cudaGetSymbolAddress((void**)&p_tmp2, g_tmp2);
    cudaGetSymbolAddress((void**)&p_hid,  g_hid);
    cudaGetSymbolAddress((void**)&p_hid2, g_hid2);
    cudaGetSymbolAddress((void**)&p_w,    g_w);

    cudaFuncSetAttribute(gemm_tf32_kernel,
                         cudaFuncAttributeMaxDynamicSharedMemorySize, SMEM_BYTES);

    // #1-#3: prepasses (slot #4 = fused projection GEMM, profiled)
    int inN  = NB*NS*(NH/4);
    build_inputs_kernel<<<(inN+255)/256, 256>>>(inputs);
    int padN = NB*(2*NW)*(NH/4);
    build_pads_kernel<<<(padN+255)/256, 256>>>(lp, rp);
    round_weights_kernel<<<(WTOT/4+255)/256, 256>>>(Wl, Wr, lw1, lw2, rw1, rw2);

    dim3 gg(NH/BN, (NB*NS)/BM, 2);   // (4, 256, 2)

    // #4: both projections in one launch (mode 2: fp32 relu out)
    gemm_tf32_kernel<<<gg, GT, SMEM_BYTES>>>(p_pad, p_pad, p_w + OFF_WL, p_w + OFF_WR,
                                             bl, br_, p_lo, p_ro, nullptr, nullptr,
                                             nullptr, nullptr, NW*NH, 1, 2, 0);

    for (int i = 0; i < NL; i++){
        size_t wsz = (size_t)NH*NH;
        float* lastp = (i == NL-1) ? out_last : nullptr;
        // LN both sides
        ln_kernel<<<(2*NB*NS)/8, 256>>>(p_lo, p_ro, lg + i*NH, rg + i*NH,
                                        lbe + i*NH, rbe + i*NH, p_tmp, p_tmp2);
        // FF1 both sides
        gemm_tf32_kernel<<<gg, GT, SMEM_BYTES>>>(p_tmp, p_tmp2,
                                                 p_w + OFF_LW1 + i*wsz, p_w + OFF_RW1 + i*wsz,
                                                 lb1 + i*NH, rb1 + i*NH, p_hid, p_hid2,
                                                 nullptr, nullptr, nullptr, nullptr,
                                                 NH, 0, 0, 0);
        // FF2 both sides + residual + scatter
        gemm_tf32_kernel<<<gg, GT, SMEM_BYTES>>>(p_hid, p_hid2,
                                                 p_w + OFF_LW2 + i*wsz, p_w + OFF_RW2 + i*wsz,
                                                 lb2 + i*NH, rb2 + i*NH, p_lo, p_ro,
                                                 p_lo, p_ro, out_all, lastp,
                                                 NH, 0, 1, i);
    }
}